// round 4
// baseline (speedup 1.0000x reference)
#include <cuda_runtime.h>

// ---------------------------------------------------------------------------
// SpanClassifier: two single-head attention logit maps with relative-position
// key bias.
//   q = (X @ Wq + bq) / sqrt(D); k = X @ Wk + bk
//   S[b,i,j] = q[b,i]·k[b,j] + (q[b,i]·rel[clip(j-i,-R,R)+R]) ; masked -> -1e18
// Stage 1: proj GEMMs (NN)      -> g_q[h], g_k[h]   (q pre-scaled by 1/32)
// Stage 2: qr = q @ rel^T (NT)  -> g_qr[h]
// Stage 3: scores (NT) + rel-bias gather + mask -> d_out (st half, ed half)
// All fp32 FFMA this round (accuracy-safe baseline); tensor-core (tcgen05
// bf16 hi/lo 3-pass) migration planned once profile data exists.
// ---------------------------------------------------------------------------

namespace cfg {
constexpr int Bn = 4, Tn = 2048, Dn = 1024, Rn = 64;
constexpr int NR = 2 * Rn + 1;     // 129
constexpr int Mrows = Bn * Tn;     // 8192
constexpr int BM = 128, BN = 128, BK = 16, TM = 8, TN = 8;
}
using namespace cfg;

// Scratch (static device allocations are allowed; cudaMalloc is not).
__device__ float g_q[2][Mrows * Dn];     // scaled queries, per head
__device__ float g_k[2][Mrows * Dn];     // keys, per head
__device__ float g_qr[2][Mrows * NR];    // q . rel_r, per head

// ---------------------------------------------------------------------------
// Stage 1: C[8192,1024] = X[8192,1024] @ W[1024,1024]; out = (C + bias)*alpha
// blockIdx.z: 0=st_q 1=st_k 2=ed_q 3=ed_k
// ---------------------------------------------------------------------------
__global__ __launch_bounds__(256, 2)
void proj_kernel(const float* __restrict__ X,
                 const float* __restrict__ Wq0, const float* __restrict__ bq0,
                 const float* __restrict__ Wk0, const float* __restrict__ bk0,
                 const float* __restrict__ Wq1, const float* __restrict__ bq1,
                 const float* __restrict__ Wk1, const float* __restrict__ bk1)
{
    __shared__ float As[BK][BM];
    __shared__ float Bs[BK][BN];

    const float* W; const float* bias; float* out; float alpha;
    switch (blockIdx.z) {
        case 0:  W = Wq0; bias = bq0; out = g_q[0]; alpha = 0.03125f; break;
        case 1:  W = Wk0; bias = bk0; out = g_k[0]; alpha = 1.0f;     break;
        case 2:  W = Wq1; bias = bq1; out = g_q[1]; alpha = 0.03125f; break;
        default: W = Wk1; bias = bk1; out = g_k[1]; alpha = 1.0f;     break;
    }

    const int tid = threadIdx.x;
    const int tx = tid & 15, ty = tid >> 4;
    const int rowBase = blockIdx.y * BM;
    const int colBase = blockIdx.x * BN;

    float acc[TM][TN] = {};

    for (int k0 = 0; k0 < Dn; k0 += BK) {
        // A tile (K-major source) -> transposed into As[k][m]
        #pragma unroll
        for (int l = 0; l < 2; l++) {
            int f = tid + l * 256;
            int r = f >> 2, c = (f & 3) << 2;
            float4 v = *reinterpret_cast<const float4*>(
                X + (size_t)(rowBase + r) * Dn + k0 + c);
            As[c + 0][r] = v.x; As[c + 1][r] = v.y;
            As[c + 2][r] = v.z; As[c + 3][r] = v.w;
        }
        // B tile (N-major source) -> direct Bs[k][n]
        #pragma unroll
        for (int l = 0; l < 2; l++) {
            int f = tid + l * 256;
            int kk = f >> 5, c = (f & 31) << 2;
            *reinterpret_cast<float4*>(&Bs[kk][c]) =
                *reinterpret_cast<const float4*>(
                    W + (size_t)(k0 + kk) * Dn + colBase + c);
        }
        __syncthreads();
        #pragma unroll
        for (int kk = 0; kk < BK; kk++) {
            float ra[TM], rb[TN];
            #pragma unroll
            for (int m = 0; m < TM; m++) ra[m] = As[kk][ty * TM + m];
            #pragma unroll
            for (int n = 0; n < TN; n++) rb[n] = Bs[kk][tx * TN + n];
            #pragma unroll
            for (int m = 0; m < TM; m++)
                #pragma unroll
                for (int n = 0; n < TN; n++)
                    acc[m][n] += ra[m] * rb[n];
        }
        __syncthreads();
    }

    #pragma unroll
    for (int m = 0; m < TM; m++) {
        int row = rowBase + ty * TM + m;
        #pragma unroll
        for (int n4 = 0; n4 < TN; n4 += 4) {
            int c0 = colBase + tx * TN + n4;
            float4 bv = *reinterpret_cast<const float4*>(bias + c0);
            float4 o;
            o.x = (acc[m][n4 + 0] + bv.x) * alpha;
            o.y = (acc[m][n4 + 1] + bv.y) * alpha;
            o.z = (acc[m][n4 + 2] + bv.z) * alpha;
            o.w = (acc[m][n4 + 3] + bv.w) * alpha;
            *reinterpret_cast<float4*>(out + (size_t)row * Dn + c0) = o;
        }
    }
}

// ---------------------------------------------------------------------------
// Stage 2: g_qr[h][m,r] = sum_d g_q[h][m,d] * rel[r,d]   (NT, N=129 bounded)
// blockIdx.z: head
// ---------------------------------------------------------------------------
__global__ __launch_bounds__(256, 2)
void qr_kernel(const float* __restrict__ rel0, const float* __restrict__ rel1)
{
    __shared__ float As[BK][BM];
    __shared__ float Bs[BK][BN];

    const int h = blockIdx.z;
    const float* Q = g_q[h];
    const float* Rel = h ? rel1 : rel0;
    float* out = g_qr[h];

    const int tid = threadIdx.x;
    const int tx = tid & 15, ty = tid >> 4;
    const int rowBase = blockIdx.y * BM;
    const int colBase = blockIdx.x * BN;

    float acc[TM][TN] = {};

    for (int k0 = 0; k0 < Dn; k0 += BK) {
        #pragma unroll
        for (int l = 0; l < 2; l++) {
            int f = tid + l * 256;
            int r = f >> 2, c = (f & 3) << 2;
            float4 v = *reinterpret_cast<const float4*>(
                Q + (size_t)(rowBase + r) * Dn + k0 + c);
            As[c + 0][r] = v.x; As[c + 1][r] = v.y;
            As[c + 2][r] = v.z; As[c + 3][r] = v.w;
        }
        #pragma unroll
        for (int l = 0; l < 2; l++) {
            int f = tid + l * 256;
            int r = f >> 2, c = (f & 3) << 2;
            int col = colBase + r;
            float4 v = make_float4(0.f, 0.f, 0.f, 0.f);
            if (col < NR)
                v = *reinterpret_cast<const float4*>(
                    Rel + (size_t)col * Dn + k0 + c);
            Bs[c + 0][r] = v.x; Bs[c + 1][r] = v.y;
            Bs[c + 2][r] = v.z; Bs[c + 3][r] = v.w;
        }
        __syncthreads();
        #pragma unroll
        for (int kk = 0; kk < BK; kk++) {
            float ra[TM], rb[TN];
            #pragma unroll
            for (int m = 0; m < TM; m++) ra[m] = As[kk][ty * TM + m];
            #pragma unroll
            for (int n = 0; n < TN; n++) rb[n] = Bs[kk][tx * TN + n];
            #pragma unroll
            for (int m = 0; m < TM; m++)
                #pragma unroll
                for (int n = 0; n < TN; n++)
                    acc[m][n] += ra[m] * rb[n];
        }
        __syncthreads();
    }

    #pragma unroll
    for (int m = 0; m < TM; m++) {
        int row = rowBase + ty * TM + m;
        #pragma unroll
        for (int n = 0; n < TN; n++) {
            int col = colBase + tx * TN + n;
            if (col < NR) out[(size_t)row * NR + col] = acc[m][n];
        }
    }
}

// ---------------------------------------------------------------------------
// Stage 3: S = q @ k^T + rel-bias gather + mask  (NT per batch/head)
// blockIdx.z in [0,8): h = z>>2 (0=st,1=ed), b = z&3
// ---------------------------------------------------------------------------
__global__ __launch_bounds__(256, 2)
void scores_kernel(const int* __restrict__ mask, float* __restrict__ gout)
{
    __shared__ float As[BK][BM];
    __shared__ float Bs[BK][BN];

    const int z = blockIdx.z;
    const int h = z >> 2;
    const int b = z & 3;

    const float* Q   = g_q[h]  + (size_t)b * Tn * Dn;
    const float* Kp  = g_k[h]  + (size_t)b * Tn * Dn;
    const float* QR  = g_qr[h] + (size_t)b * Tn * NR;
    const int*   Msk = mask    + (size_t)b * Tn * Tn;
    float*       Out = gout + (size_t)h * Bn * Tn * Tn + (size_t)b * Tn * Tn;

    const int tid = threadIdx.x;
    const int tx = tid & 15, ty = tid >> 4;
    const int rowBase = blockIdx.y * BM;
    const int colBase = blockIdx.x * BN;

    float acc[TM][TN] = {};

    for (int k0 = 0; k0 < Dn; k0 += BK) {
        #pragma unroll
        for (int l = 0; l < 2; l++) {
            int f = tid + l * 256;
            int r = f >> 2, c = (f & 3) << 2;
            float4 v = *reinterpret_cast<const float4*>(
                Q + (size_t)(rowBase + r) * Dn + k0 + c);
            As[c + 0][r] = v.x; As[c + 1][r] = v.y;
            As[c + 2][r] = v.z; As[c + 3][r] = v.w;
        }
        #pragma unroll
        for (int l = 0; l < 2; l++) {
            int f = tid + l * 256;
            int r = f >> 2, c = (f & 3) << 2;
            float4 v = *reinterpret_cast<const float4*>(
                Kp + (size_t)(colBase + r) * Dn + k0 + c);
            Bs[c + 0][r] = v.x; Bs[c + 1][r] = v.y;
            Bs[c + 2][r] = v.z; Bs[c + 3][r] = v.w;
        }
        __syncthreads();
        #pragma unroll
        for (int kk = 0; kk < BK; kk++) {
            float ra[TM], rb[TN];
            #pragma unroll
            for (int m = 0; m < TM; m++) ra[m] = As[kk][ty * TM + m];
            #pragma unroll
            for (int n = 0; n < TN; n++) rb[n] = Bs[kk][tx * TN + n];
            #pragma unroll
            for (int m = 0; m < TM; m++)
                #pragma unroll
                for (int n = 0; n < TN; n++)
                    acc[m][n] += ra[m] * rb[n];
        }
        __syncthreads();
    }

    // Epilogue: add qr[b,i,clip(j-i,-R,R)+R], apply mask, write.
    #pragma unroll
    for (int m = 0; m < TM; m++) {
        const int i = rowBase + ty * TM + m;
        const int ibase = i * Tn;
        const float* qr_row = QR + (size_t)i * NR;
        #pragma unroll
        for (int n4 = 0; n4 < TN; n4 += 4) {
            const int j0 = colBase + tx * TN + n4;
            float v[4];
            #pragma unroll
            for (int e = 0; e < 4; e++) {
                int d = j0 + e - i;
                d = d < -Rn ? -Rn : (d > Rn ? Rn : d);
                v[e] = acc[m][n4 + e] + qr_row[d + Rn];
            }
            int4 mk = *reinterpret_cast<const int4*>(Msk + ibase + j0);
            float4 o;
            o.x = mk.x ? v[0] : -1e18f;
            o.y = mk.y ? v[1] : -1e18f;
            o.z = mk.z ? v[2] : -1e18f;
            o.w = mk.w ? v[3] : -1e18f;
            *reinterpret_cast<float4*>(Out + ibase + j0) = o;
        }
    }
}

// ---------------------------------------------------------------------------
// Launch. Inputs (metadata order): repre, mask, st_Wq, st_bq, st_Wk, st_bk,
// st_rel, ed_Wq, ed_bq, ed_Wk, ed_bk, ed_rel. Output: [st | ed] fp32.
// ---------------------------------------------------------------------------
extern "C" void kernel_launch(void* const* d_in, const int* in_sizes, int n_in,
                              void* d_out, int out_size)
{
    (void)in_sizes; (void)n_in; (void)out_size;
    const float* repre  = (const float*)d_in[0];
    const int*   mask   = (const int*)  d_in[1];
    const float* st_Wq  = (const float*)d_in[2];
    const float* st_bq  = (const float*)d_in[3];
    const float* st_Wk  = (const float*)d_in[4];
    const float* st_bk  = (const float*)d_in[5];
    const float* st_rel = (const float*)d_in[6];
    const float* ed_Wq  = (const float*)d_in[7];
    const float* ed_bq  = (const float*)d_in[8];
    const float* ed_Wk  = (const float*)d_in[9];
    const float* ed_bk  = (const float*)d_in[10];
    const float* ed_rel = (const float*)d_in[11];
    float* out = (float*)d_out;

    dim3 blk(256);

    // Stage 1: projections (4 GEMMs via grid.z)
    proj_kernel<<<dim3(Dn / BN, Mrows / BM, 4), blk>>>(
        repre, st_Wq, st_bq, st_Wk, st_bk, ed_Wq, ed_bq, ed_Wk, ed_bk);

    // Stage 2: qr = q @ rel^T (2 heads via grid.z; N=129 -> 2 col tiles)
    qr_kernel<<<dim3((NR + BN - 1) / BN, Mrows / BM, 2), blk>>>(st_rel, ed_rel);

    // Stage 3: scores + rel bias + mask (8 batch*head slices via grid.z)
    scores_kernel<<<dim3(Tn / BN, Tn / BM, 8), blk>>>(mask, out);
}